// round 8
// baseline (speedup 1.0000x reference)
#include <cuda_runtime.h>
#include <cuda_bf16.h>

// Problem constants
#define T_DIM 32768
#define D_DIM 1024
#define L_CHUNK 32
#define C_CHUNKS (T_DIM / L_CHUNK)      // 1024
#define SUPER 16                        // chunks per super-chunk
#define NSUP (C_CHUNKS / SUPER)         // 64 super-chunks

#define ETA_MU_F 0.01f
#define A_MU_F   0.99f
#define ETA_V_F  0.02f
#define CV_F     0.98f

// Static device scratch (no allocation allowed).
// Per-chunk aggregate, AoS: (cmu, P, Q, sum) + separate ss.
__device__ float4 g_agg[C_CHUNKS * D_DIM];
__device__ float  g_ss[C_CHUNKS * D_DIM];
// Per-chunk entry state, paired (mu,var): stored as float4 covering 2 columns.
__device__ float4 g_state[C_CHUNKS * D_DIM / 2];
// Per-super-chunk aggregates / entry states:
__device__ float4 s_agg[NSUP * D_DIM];      // (c, P, Q, sum)
__device__ float  s_ss[NSUP * D_DIM];
__device__ float  s_mus[NSUP * D_DIM];
__device__ float  s_vas[NSUP * D_DIM];

// Per-chunk constants over literals: fully unrolled so ptxas constant-folds
// the double-precision preamble.
__device__ __forceinline__ void chunk_consts(float& Amc, float& Avc, float& Rc) {
    double Am = 1.0, Av = 1.0, R = 0.0, g2 = 0.9801;  // a^2
    #pragma unroll
    for (int i = 0; i < L_CHUNK; i++) {
        Am *= 0.99; Av *= 0.98;
        R = R * 0.98 + 0.02 * g2;
        g2 *= 0.9801;
    }
    Amc = (float)Am; Avc = (float)Av; Rc = (float)R;
}

// ---------------------------------------------------------------------------
// Pass 1: one vectorized read of x -> per-chunk aggregates (AoS).
//   u_i = x_i - m_i (m = zero-state chunk EWMA)
//   Pa = sum cv^{L-1-i} u_i^2, Qa = sum cv^{L-1-i} u_i a^{i+1}
// Each thread owns 4 adjacent columns (float4 input). Grid (2, 1024).
// ---------------------------------------------------------------------------
__global__ __launch_bounds__(128) void p1_kernel(const float4* __restrict__ x4) {
    const int d4 = blockIdx.x * blockDim.x + threadIdx.x;   // column group 0..255
    const int c  = blockIdx.y;
    const float4* xp = x4 + (size_t)c * L_CHUNK * (D_DIM / 4) + d4;

    float m[4]   = {0.f,0.f,0.f,0.f};
    float sum[4] = {0.f,0.f,0.f,0.f};
    float ss[4]  = {0.f,0.f,0.f,0.f};
    float Pa[4]  = {0.f,0.f,0.f,0.f};
    float Qa[4]  = {0.f,0.f,0.f,0.f};
    float g = A_MU_F;  // a^{i+1}

    #pragma unroll 8
    for (int i = 0; i < L_CHUNK; i++) {
        float4 xv4 = xp[(size_t)i * (D_DIM / 4)];
        float xv[4] = {xv4.x, xv4.y, xv4.z, xv4.w};
        #pragma unroll
        for (int k = 0; k < 4; k++) {
            float v = xv[k];
            sum[k] += v;
            ss[k] = fmaf(v, v, ss[k]);
            m[k] = fmaf(ETA_MU_F, v - m[k], m[k]);   // reference rounding form
            float u = v - m[k];
            Pa[k] = fmaf(CV_F, Pa[k], u * u);
            Qa[k] = fmaf(CV_F, Qa[k], u * g);
        }
        g *= A_MU_F;
    }
    const int base = c * D_DIM + d4 * 4;
    #pragma unroll
    for (int k = 0; k < 4; k++) {
        g_agg[base + k] = make_float4(m[k], ETA_V_F * Pa[k], ETA_V_F * Qa[k], sum[k]);
        g_ss[base + k]  = ss[k];
    }
}

// ---------------------------------------------------------------------------
// Pass 2a: compose SUPER chunk aggregates -> one super-chunk aggregate.
// One thread per (super-chunk, column): 65536 threads, coalesced over d.
//   P' = Avc*P + (Pb - 2 Qb c + Rc c^2)
//   Q' = Avc*Q + Am*(Qb - Rc*c)
//   c' = Amc*c + cb ;  Am' = Amc*Am
// ---------------------------------------------------------------------------
__global__ __launch_bounds__(256) void p2a_kernel() {
    const int tid = blockIdx.x * blockDim.x + threadIdx.x;
    const int d = tid % D_DIM;
    const int gsup = tid / D_DIM;
    if (gsup >= NSUP) return;

    float Amc, Avc, Rc;
    chunk_consts(Amc, Avc, Rc);

    float c = 0.f, P = 0.f, Q = 0.f, Am = 1.f;
    float psum = 0.f, pss = 0.f;

    int idx = gsup * SUPER * D_DIM + d;
    #pragma unroll
    for (int j = 0; j < SUPER; j++, idx += D_DIM) {
        float4 ag = g_agg[idx];            // (cb, Pb, Qb, sumb)
        float ssb = g_ss[idx];
        psum += ag.w;
        pss  += ssb;
        P = fmaf(Avc, P, fmaf(c, fmaf(Rc, c, -2.f * ag.z), ag.y));  // Avc*P + Pb - 2Qb c + Rc c^2
        Q = fmaf(Avc, Q, Am * fmaf(-Rc, c, ag.z));                   // Avc*Q + Am*(Qb - Rc c)
        c = fmaf(Amc, c, ag.x);
        Am *= Amc;
    }
    const int sidx = gsup * D_DIM + d;
    s_agg[sidx] = make_float4(c, P, Q, psum);
    s_ss[sidx]  = pss;
}

// ---------------------------------------------------------------------------
// Pass 2b: per column. Reduce NSUP partial sums -> mu0/var0 (double), then
// fold NSUP super aggregates serially -> per-super entry states.
// ---------------------------------------------------------------------------
__global__ __launch_bounds__(256) void p2b_kernel() {
    const int d = blockIdx.x * blockDim.x + threadIdx.x;
    if (d >= D_DIM) return;

    double tsum = 0.0, tss = 0.0;
    #pragma unroll 8
    for (int g = 0; g < NSUP; g++) {
        tsum += (double)s_agg[g * D_DIM + d].w;
        tss  += (double)s_ss[g * D_DIM + d];
    }
    const double Td = (double)T_DIM;
    float mu0  = (float)(tsum / Td);
    float var0 = (float)sqrt((tss - tsum * tsum / Td) / (Td - 1.0));

    // chunk constants, then super-level Am_s, Av_s, R_s (fold SUPER chunks)
    float Amc, Avc, Rc;
    chunk_consts(Amc, Avc, Rc);
    double Rs = 0.0, Amd = 1.0, Avs = 1.0, Ams = 1.0;
    #pragma unroll
    for (int j = 0; j < SUPER; j++) {
        Rs = (double)Avc * Rs + (double)Rc * Amd * Amd;
        Amd *= (double)Amc;
        Avs *= (double)Avc;
        Ams *= (double)Amc;
    }
    const float Am_s = (float)Ams, Av_s = (float)Avs, R_s = (float)Rs;

    float s = mu0, v = var0;
    #pragma unroll 8
    for (int g = 0; g < NSUP; g++) {
        const int sidx = g * D_DIM + d;
        s_mus[sidx] = s;
        s_vas[sidx] = v;
        float4 ag = s_agg[sidx];
        v = fmaf(Av_s, v, fmaf(s, fmaf(s, R_s, -2.f * ag.z), ag.y));
        s = fmaf(Am_s, s, ag.x);
    }
}

// ---------------------------------------------------------------------------
// Pass 2c: expand within each super-chunk -> per-chunk entry states.
// One thread per (super-chunk, column): 65536 threads, SUPER steps each.
// One LDG.128 + one STG.64 per step.
// ---------------------------------------------------------------------------
__global__ __launch_bounds__(256) void p2c_kernel() {
    const int tid = blockIdx.x * blockDim.x + threadIdx.x;
    const int d = tid % D_DIM;
    const int gsup = tid / D_DIM;
    if (gsup >= NSUP) return;

    float Amc, Avc, Rc;
    chunk_consts(Amc, Avc, Rc);

    const int sidx = gsup * D_DIM + d;
    float s = s_mus[sidx];
    float v = s_vas[sidx];

    float2* __restrict__ st2 = (float2*)g_state;
    int idx = gsup * SUPER * D_DIM + d;
    #pragma unroll
    for (int j = 0; j < SUPER; j++, idx += D_DIM) {
        st2[idx] = make_float2(s, v);
        float4 ag = g_agg[idx];
        v = fmaf(Avc, v, fmaf(s, fmaf(s, Rc, -2.f * ag.z), ag.y));
        s = fmaf(Amc, s, ag.x);
    }
}

// ---------------------------------------------------------------------------
// Pass 5: second vectorized read of x. Replay each chunk serially with the
// exact fp32 arithmetic of the reference; write norm, mu, var as float4.
// ---------------------------------------------------------------------------
__global__ __launch_bounds__(128) void p5_kernel(const float4* __restrict__ x4,
                                                 float4* __restrict__ out4) {
    float4* __restrict__ norm = out4;                                  // [T, D/4]
    float4* __restrict__ info = out4 + (size_t)T_DIM * (D_DIM / 4);    // [T, 2D/4]

    const int d4 = blockIdx.x * blockDim.x + threadIdx.x;  // 0..255
    const int c  = blockIdx.y;
    const int d0 = d4 * 4;

    // Entry state: 2 LDG.128 covering 4 columns' (mu,var) pairs.
    float4 sa = g_state[(c * D_DIM + d0) / 2];      // (mu0,var0,mu1,var1)
    float4 sb = g_state[(c * D_DIM + d0) / 2 + 1];  // (mu2,var2,mu3,var3)
    float mu[4]  = {sa.x, sa.z, sb.x, sb.z};
    float var[4] = {sa.y, sa.w, sb.y, sb.w};

    const size_t tbase = (size_t)c * L_CHUNK;
    #pragma unroll 4
    for (int i = 0; i < L_CHUNK; i++) {
        const size_t t = tbase + i;
        float4 xv4 = x4[t * (D_DIM / 4) + d4];
        float xv[4] = {xv4.x, xv4.y, xv4.z, xv4.w};
        float nv[4];
        #pragma unroll
        for (int k = 0; k < 4; k++) {
            mu[k] = fmaf(ETA_MU_F, xv[k] - mu[k], mu[k]);          // mu += eta*(x-mu)
            float dd = xv[k] - mu[k];
            var[k] = fmaf(ETA_V_F, dd * dd, CV_F * var[k]);         // 0.98*var + 0.02*dd^2
            nv[k] = dd * rsqrtf(var[k]);                            // (x-mu)/sqrt(var)
        }
        norm[t * (D_DIM / 4) + d4]                    = make_float4(nv[0], nv[1], nv[2], nv[3]);
        info[t * (2 * D_DIM / 4) + d4]                = make_float4(mu[0], mu[1], mu[2], mu[3]);
        info[t * (2 * D_DIM / 4) + (D_DIM / 4) + d4]  = make_float4(var[0], var[1], var[2], var[3]);
    }
}

extern "C" void kernel_launch(void* const* d_in, const int* in_sizes, int n_in,
                              void* d_out, int out_size) {
    const float4* x4 = (const float4*)d_in[0];
    float4* out4 = (float4*)d_out;

    dim3 b(128);
    dim3 g1((D_DIM / 4) / 128, C_CHUNKS);   // (2, 1024)
    p1_kernel<<<g1, b>>>(x4);
    p2a_kernel<<<(NSUP * D_DIM) / 256, 256>>>();
    p2b_kernel<<<D_DIM / 256, 256>>>();
    p2c_kernel<<<(NSUP * D_DIM) / 256, 256>>>();
    p5_kernel<<<g1, b>>>(x4, out4);
}

// round 9
// speedup vs baseline: 1.0339x; 1.0339x over previous
#include <cuda_runtime.h>
#include <cuda_bf16.h>

// Problem constants
#define T_DIM 32768
#define D_DIM 1024
#define L_CHUNK 32
#define C_CHUNKS (T_DIM / L_CHUNK)      // 1024
#define SUPER 16                        // chunks per super-chunk
#define NSUP (C_CHUNKS / SUPER)         // 64 super-chunks

#define ETA_MU_F 0.01f
#define A_MU_F   0.99f
#define ETA_V_F  0.02f
#define CV_F     0.98f

// Static device scratch (no allocation allowed).
// Per-chunk aggregate, AoS: (cmu, P, Q, sum) + separate ss.
__device__ float4 g_agg[C_CHUNKS * D_DIM];
__device__ float  g_ss[C_CHUNKS * D_DIM];
// Per-chunk entry state, paired (mu,var): float4 covers 2 columns.
__device__ float4 g_state[C_CHUNKS * D_DIM / 2];
// Per-super-chunk aggregates / entry states:
__device__ float4 s_agg[NSUP * D_DIM];      // (c, P, Q, sum)
__device__ float  s_ss[NSUP * D_DIM];
__device__ float  s_mus[NSUP * D_DIM];
__device__ float  s_vas[NSUP * D_DIM];

// Per-chunk constants over literals: fully unrolled so ptxas constant-folds
// the double-precision preamble.
__device__ __forceinline__ void chunk_consts(float& Amc, float& Avc, float& Rc) {
    double Am = 1.0, Av = 1.0, R = 0.0, g2 = 0.9801;  // a^2
    #pragma unroll
    for (int i = 0; i < L_CHUNK; i++) {
        Am *= 0.99; Av *= 0.98;
        R = R * 0.98 + 0.02 * g2;
        g2 *= 0.9801;
    }
    Amc = (float)Am; Avc = (float)Av; Rc = (float)R;
}

// ---------------------------------------------------------------------------
// Pass 1: one streaming read of x -> per-chunk aggregates (AoS).
// ONE COLUMN PER THREAD: lane-contiguous LDG.32 input, lane-contiguous
// STG.128 aggregate output, ~20 regs -> near-full occupancy.
// Grid (4, 1024), block 256: 1,048,576 threads.
// ---------------------------------------------------------------------------
__global__ __launch_bounds__(256) void p1_kernel(const float* __restrict__ x) {
    const int d = blockIdx.x * blockDim.x + threadIdx.x;   // column 0..1023
    const int c = blockIdx.y;
    const float* xp = x + (size_t)c * L_CHUNK * D_DIM + d;

    float m = 0.f, sum = 0.f, ss = 0.f, Pa = 0.f, Qa = 0.f;
    float g = A_MU_F;  // a^{i+1}

    #pragma unroll 8
    for (int i = 0; i < L_CHUNK; i++) {
        float v = __ldcs(xp + (size_t)i * D_DIM);
        sum += v;
        ss = fmaf(v, v, ss);
        m = fmaf(ETA_MU_F, v - m, m);        // reference rounding form
        float u = v - m;
        Pa = fmaf(CV_F, Pa, u * u);
        Qa = fmaf(CV_F, Qa, u * g);
        g *= A_MU_F;
    }
    const int idx = c * D_DIM + d;
    g_agg[idx] = make_float4(m, ETA_V_F * Pa, ETA_V_F * Qa, sum);
    g_ss[idx]  = ss;
}

// ---------------------------------------------------------------------------
// Pass 2a: compose SUPER chunk aggregates -> one super-chunk aggregate.
// One thread per (super-chunk, column): 65536 threads, coalesced over d.
//   P' = Avc*P + (Pb - 2 Qb c + Rc c^2)
//   Q' = Avc*Q + Am*(Qb - Rc*c)
//   c' = Amc*c + cb ;  Am' = Amc*Am
// ---------------------------------------------------------------------------
__global__ __launch_bounds__(256) void p2a_kernel() {
    const int tid = blockIdx.x * blockDim.x + threadIdx.x;
    const int d = tid % D_DIM;
    const int gsup = tid / D_DIM;
    if (gsup >= NSUP) return;

    float Amc, Avc, Rc;
    chunk_consts(Amc, Avc, Rc);

    float c = 0.f, P = 0.f, Q = 0.f, Am = 1.f;
    float psum = 0.f, pss = 0.f;

    int idx = gsup * SUPER * D_DIM + d;
    #pragma unroll
    for (int j = 0; j < SUPER; j++, idx += D_DIM) {
        float4 ag = g_agg[idx];            // (cb, Pb, Qb, sumb)
        float ssb = g_ss[idx];
        psum += ag.w;
        pss  += ssb;
        P = fmaf(Avc, P, fmaf(c, fmaf(Rc, c, -2.f * ag.z), ag.y));  // Avc*P + Pb - 2Qb c + Rc c^2
        Q = fmaf(Avc, Q, Am * fmaf(-Rc, c, ag.z));                   // Avc*Q + Am*(Qb - Rc c)
        c = fmaf(Amc, c, ag.x);
        Am *= Amc;
    }
    const int sidx = gsup * D_DIM + d;
    s_agg[sidx] = make_float4(c, P, Q, psum);
    s_ss[sidx]  = pss;
}

// ---------------------------------------------------------------------------
// Pass 2b: per column. Reduce NSUP partial sums -> mu0/var0 (double), then
// fold NSUP super aggregates serially -> per-super entry states.
// ---------------------------------------------------------------------------
__global__ __launch_bounds__(256) void p2b_kernel() {
    const int d = blockIdx.x * blockDim.x + threadIdx.x;
    if (d >= D_DIM) return;

    double tsum = 0.0, tss = 0.0;
    #pragma unroll 8
    for (int g = 0; g < NSUP; g++) {
        tsum += (double)s_agg[g * D_DIM + d].w;
        tss  += (double)s_ss[g * D_DIM + d];
    }
    const double Td = (double)T_DIM;
    float mu0  = (float)(tsum / Td);
    float var0 = (float)sqrt((tss - tsum * tsum / Td) / (Td - 1.0));

    // chunk constants, then super-level Am_s, Av_s, R_s (fold SUPER chunks)
    float Amc, Avc, Rc;
    chunk_consts(Amc, Avc, Rc);
    double Rs = 0.0, Amd = 1.0, Avs = 1.0, Ams = 1.0;
    #pragma unroll
    for (int j = 0; j < SUPER; j++) {
        Rs = (double)Avc * Rs + (double)Rc * Amd * Amd;
        Amd *= (double)Amc;
        Avs *= (double)Avc;
        Ams *= (double)Amc;
    }
    const float Am_s = (float)Ams, Av_s = (float)Avs, R_s = (float)Rs;

    float s = mu0, v = var0;
    #pragma unroll 8
    for (int g = 0; g < NSUP; g++) {
        const int sidx = g * D_DIM + d;
        s_mus[sidx] = s;
        s_vas[sidx] = v;
        float4 ag = s_agg[sidx];
        v = fmaf(Av_s, v, fmaf(s, fmaf(s, R_s, -2.f * ag.z), ag.y));
        s = fmaf(Am_s, s, ag.x);
    }
}

// ---------------------------------------------------------------------------
// Pass 2c: expand within each super-chunk -> per-chunk entry states.
// One thread per (super-chunk, column): 65536 threads, SUPER steps each.
// One LDG.128 + one STG.64 per step, all coalesced.
// ---------------------------------------------------------------------------
__global__ __launch_bounds__(256) void p2c_kernel() {
    const int tid = blockIdx.x * blockDim.x + threadIdx.x;
    const int d = tid % D_DIM;
    const int gsup = tid / D_DIM;
    if (gsup >= NSUP) return;

    float Amc, Avc, Rc;
    chunk_consts(Amc, Avc, Rc);

    const int sidx = gsup * D_DIM + d;
    float s = s_mus[sidx];
    float v = s_vas[sidx];

    float2* __restrict__ st2 = (float2*)g_state;
    int idx = gsup * SUPER * D_DIM + d;
    #pragma unroll
    for (int j = 0; j < SUPER; j++, idx += D_DIM) {
        st2[idx] = make_float2(s, v);
        float4 ag = g_agg[idx];
        v = fmaf(Avc, v, fmaf(s, fmaf(s, Rc, -2.f * ag.z), ag.y));
        s = fmaf(Amc, s, ag.x);
    }
}

// ---------------------------------------------------------------------------
// Pass 5: second streaming read of x. Replay each chunk serially with the
// exact fp32 arithmetic of the reference; write norm, mu, var as streaming
// STG.128 (no L2 pollution of the scratch arrays).
// ---------------------------------------------------------------------------
__global__ __launch_bounds__(128) void p5_kernel(const float4* __restrict__ x4,
                                                 float4* __restrict__ out4) {
    float4* __restrict__ norm = out4;                                  // [T, D/4]
    float4* __restrict__ info = out4 + (size_t)T_DIM * (D_DIM / 4);    // [T, 2D/4]

    const int d4 = blockIdx.x * blockDim.x + threadIdx.x;  // 0..255
    const int c  = blockIdx.y;
    const int d0 = d4 * 4;

    // Entry state: 2 LDG.128 covering 4 columns' (mu,var) pairs.
    float4 sa = g_state[(c * D_DIM + d0) / 2];      // (mu0,var0,mu1,var1)
    float4 sb = g_state[(c * D_DIM + d0) / 2 + 1];  // (mu2,var2,mu3,var3)
    float mu[4]  = {sa.x, sa.z, sb.x, sb.z};
    float var[4] = {sa.y, sa.w, sb.y, sb.w};

    const size_t tbase = (size_t)c * L_CHUNK;
    #pragma unroll 4
    for (int i = 0; i < L_CHUNK; i++) {
        const size_t t = tbase + i;
        float4 xv4 = __ldcs(&x4[t * (D_DIM / 4) + d4]);
        float xv[4] = {xv4.x, xv4.y, xv4.z, xv4.w};
        float nv[4];
        #pragma unroll
        for (int k = 0; k < 4; k++) {
            mu[k] = fmaf(ETA_MU_F, xv[k] - mu[k], mu[k]);          // mu += eta*(x-mu)
            float dd = xv[k] - mu[k];
            var[k] = fmaf(ETA_V_F, dd * dd, CV_F * var[k]);         // 0.98*var + 0.02*dd^2
            nv[k] = dd * rsqrtf(var[k]);                            // (x-mu)/sqrt(var)
        }
        __stcs(&norm[t * (D_DIM / 4) + d4],
               make_float4(nv[0], nv[1], nv[2], nv[3]));
        __stcs(&info[t * (2 * D_DIM / 4) + d4],
               make_float4(mu[0], mu[1], mu[2], mu[3]));
        __stcs(&info[t * (2 * D_DIM / 4) + (D_DIM / 4) + d4],
               make_float4(var[0], var[1], var[2], var[3]));
    }
}

extern "C" void kernel_launch(void* const* d_in, const int* in_sizes, int n_in,
                              void* d_out, int out_size) {
    const float* x = (const float*)d_in[0];
    const float4* x4 = (const float4*)d_in[0];
    float4* out4 = (float4*)d_out;

    p1_kernel<<<dim3(D_DIM / 256, C_CHUNKS), 256>>>(x);
    p2a_kernel<<<(NSUP * D_DIM) / 256, 256>>>();
    p2b_kernel<<<D_DIM / 256, 256>>>();
    p2c_kernel<<<(NSUP * D_DIM) / 256, 256>>>();
    p5_kernel<<<dim3((D_DIM / 4) / 128, C_CHUNKS), 128>>>(x4, out4);
}

// round 14
// speedup vs baseline: 1.0513x; 1.0168x over previous
#include <cuda_runtime.h>
#include <cuda_bf16.h>

// Problem constants
#define T_DIM 32768
#define D_DIM 1024
#define L_CHUNK 32
#define C_CHUNKS (T_DIM / L_CHUNK)      // 1024
#define SUPER 16                        // chunks per super-chunk
#define NSUP (C_CHUNKS / SUPER)         // 64 super-chunks

#define ETA_MU_F 0.01f
#define A_MU_F   0.99f
#define ETA_V_F  0.02f
#define CV_F     0.98f

// Static device scratch (no allocation allowed).
// Per-chunk aggregate, AoS: (cmu, P, Q, sum) + separate ss.
__device__ float4 g_agg[C_CHUNKS * D_DIM];
__device__ float  g_ss[C_CHUNKS * D_DIM];
// Per-chunk entry state (mu,var), native float2 so stores carry no-alias info.
__device__ float2 g_state[C_CHUNKS * D_DIM];
// Per-super-chunk aggregates / entry states:
__device__ float4 s_agg[NSUP * D_DIM];      // (c, P, Q, sum)
__device__ float  s_ss[NSUP * D_DIM];
__device__ float  s_mus[NSUP * D_DIM];
__device__ float  s_vas[NSUP * D_DIM];

// Per-chunk constants over literals: fully unrolled so ptxas constant-folds
// the double-precision preamble.
__device__ __forceinline__ void chunk_consts(float& Amc, float& Avc, float& Rc) {
    double Am = 1.0, Av = 1.0, R = 0.0, g2 = 0.9801;  // a^2
    #pragma unroll
    for (int i = 0; i < L_CHUNK; i++) {
        Am *= 0.99; Av *= 0.98;
        R = R * 0.98 + 0.02 * g2;
        g2 *= 0.9801;
    }
    Amc = (float)Am; Avc = (float)Av; Rc = (float)R;
}

// ---------------------------------------------------------------------------
// Pass 1: one streaming read of x -> per-chunk aggregates (AoS).
// One column per thread: lane-contiguous LDG.32 input, lane-contiguous
// STG.128 aggregate output. Grid (4, 1024), block 256: 1,048,576 threads.
// ---------------------------------------------------------------------------
__global__ __launch_bounds__(256) void p1_kernel(const float* __restrict__ x) {
    const int d = blockIdx.x * blockDim.x + threadIdx.x;   // column 0..1023
    const int c = blockIdx.y;
    const float* xp = x + (size_t)c * L_CHUNK * D_DIM + d;

    float m = 0.f, sum = 0.f, ss = 0.f, Pa = 0.f, Qa = 0.f;
    float g = A_MU_F;  // a^{i+1}

    #pragma unroll 8
    for (int i = 0; i < L_CHUNK; i++) {
        float v = __ldcs(xp + (size_t)i * D_DIM);
        sum += v;
        ss = fmaf(v, v, ss);
        m = fmaf(ETA_MU_F, v - m, m);        // reference rounding form
        float u = v - m;
        Pa = fmaf(CV_F, Pa, u * u);
        Qa = fmaf(CV_F, Qa, u * g);
        g *= A_MU_F;
    }
    const int idx = c * D_DIM + d;
    g_agg[idx] = make_float4(m, ETA_V_F * Pa, ETA_V_F * Qa, sum);
    g_ss[idx]  = ss;
}

// ---------------------------------------------------------------------------
// Pass 2a: compose SUPER chunk aggregates -> one super-chunk aggregate.
// One thread per (super-chunk, column). All SUPER aggregates prefetched in
// one unrolled batch (MLP=16), then folded from registers.
// ---------------------------------------------------------------------------
__global__ __launch_bounds__(256) void p2a_kernel() {
    const int tid = blockIdx.x * blockDim.x + threadIdx.x;
    const int d = tid % D_DIM;
    const int gsup = tid / D_DIM;
    if (gsup >= NSUP) return;

    float Amc, Avc, Rc;
    chunk_consts(Amc, Avc, Rc);

    // Batch-prefetch all SUPER aggregates (independent loads, back-to-back).
    float4 ag[SUPER];
    float  ssb[SUPER];
    {
        const int base = gsup * SUPER * D_DIM + d;
        #pragma unroll
        for (int j = 0; j < SUPER; j++) {
            ag[j]  = g_agg[base + j * D_DIM];
            ssb[j] = g_ss[base + j * D_DIM];
        }
    }

    float c = 0.f, P = 0.f, Q = 0.f, Am = 1.f;
    float psum = 0.f, pss = 0.f;
    #pragma unroll
    for (int j = 0; j < SUPER; j++) {
        psum += ag[j].w;
        pss  += ssb[j];
        P = fmaf(Avc, P, fmaf(c, fmaf(Rc, c, -2.f * ag[j].z), ag[j].y)); // Avc*P + Pb - 2Qb c + Rc c^2
        Q = fmaf(Avc, Q, Am * fmaf(-Rc, c, ag[j].z));                     // Avc*Q + Am*(Qb - Rc c)
        c = fmaf(Amc, c, ag[j].x);
        Am *= Amc;
    }
    const int sidx = gsup * D_DIM + d;
    s_agg[sidx] = make_float4(c, P, Q, psum);
    s_ss[sidx]  = pss;
}

// ---------------------------------------------------------------------------
// Pass 2b: per column. Reduce NSUP partial sums -> mu0/var0 (double), then
// fold NSUP super aggregates serially -> per-super entry states.
// ---------------------------------------------------------------------------
__global__ __launch_bounds__(256) void p2b_kernel() {
    const int d = blockIdx.x * blockDim.x + threadIdx.x;
    if (d >= D_DIM) return;

    double tsum = 0.0, tss = 0.0;
    #pragma unroll 8
    for (int g = 0; g < NSUP; g++) {
        tsum += (double)s_agg[g * D_DIM + d].w;
        tss  += (double)s_ss[g * D_DIM + d];
    }
    const double Td = (double)T_DIM;
    float mu0  = (float)(tsum / Td);
    float var0 = (float)sqrt((tss - tsum * tsum / Td) / (Td - 1.0));

    // chunk constants, then super-level Am_s, Av_s, R_s (fold SUPER chunks)
    float Amc, Avc, Rc;
    chunk_consts(Amc, Avc, Rc);
    double Rs = 0.0, Amd = 1.0, Avs = 1.0, Ams = 1.0;
    #pragma unroll
    for (int j = 0; j < SUPER; j++) {
        Rs = (double)Avc * Rs + (double)Rc * Amd * Amd;
        Amd *= (double)Amc;
        Avs *= (double)Avc;
        Ams *= (double)Amc;
    }
    const float Am_s = (float)Ams, Av_s = (float)Avs, R_s = (float)Rs;

    float s = mu0, v = var0;
    #pragma unroll 8
    for (int g = 0; g < NSUP; g++) {
        const int sidx = g * D_DIM + d;
        s_mus[sidx] = s;
        s_vas[sidx] = v;
        float4 ag = s_agg[sidx];
        v = fmaf(Av_s, v, fmaf(s, fmaf(s, R_s, -2.f * ag.z), ag.y));
        s = fmaf(Am_s, s, ag.x);
    }
}

// ---------------------------------------------------------------------------
// Pass 2c: expand within each super-chunk -> per-chunk entry states.
// Batch-prefetch all SUPER aggregates first (MLP=16), THEN compute + store.
// No cast pointers: stores to float2 g_state can't alias float4 g_agg, and
// all loads are issued before any store regardless.
// ---------------------------------------------------------------------------
__global__ __launch_bounds__(256) void p2c_kernel() {
    const int tid = blockIdx.x * blockDim.x + threadIdx.x;
    const int d = tid % D_DIM;
    const int gsup = tid / D_DIM;
    if (gsup >= NSUP) return;

    float Amc, Avc, Rc;
    chunk_consts(Amc, Avc, Rc);

    // Batch-prefetch all aggregates for this super-chunk.
    float4 ag[SUPER];
    {
        const int base = gsup * SUPER * D_DIM + d;
        #pragma unroll
        for (int j = 0; j < SUPER; j++)
            ag[j] = g_agg[base + j * D_DIM];
    }

    const int sidx = gsup * D_DIM + d;
    float s = s_mus[sidx];
    float v = s_vas[sidx];

    int idx = gsup * SUPER * D_DIM + d;
    #pragma unroll
    for (int j = 0; j < SUPER; j++, idx += D_DIM) {
        g_state[idx] = make_float2(s, v);
        v = fmaf(Avc, v, fmaf(s, fmaf(s, Rc, -2.f * ag[j].z), ag[j].y));
        s = fmaf(Amc, s, ag[j].x);
    }
}

// ---------------------------------------------------------------------------
// Pass 5: second streaming read of x. Replay each chunk serially with the
// exact fp32 arithmetic of the reference; write norm, mu, var as streaming
// STG.128.
// ---------------------------------------------------------------------------
__global__ __launch_bounds__(128) void p5_kernel(const float4* __restrict__ x4,
                                                 float4* __restrict__ out4) {
    float4* __restrict__ norm = out4;                                  // [T, D/4]
    float4* __restrict__ info = out4 + (size_t)T_DIM * (D_DIM / 4);    // [T, 2D/4]

    const int d4 = blockIdx.x * blockDim.x + threadIdx.x;  // 0..255
    const int c  = blockIdx.y;
    const int d0 = d4 * 4;

    // Entry state: 2 LDG.128 covering 4 columns' (mu,var) pairs.
    const float4* st4 = (const float4*)g_state;
    float4 sa = st4[(c * D_DIM + d0) / 2];      // (mu0,var0,mu1,var1)
    float4 sb = st4[(c * D_DIM + d0) / 2 + 1];  // (mu2,var2,mu3,var3)
    float mu[4]  = {sa.x, sa.z, sb.x, sb.z};
    float var[4] = {sa.y, sa.w, sb.y, sb.w};

    const size_t tbase = (size_t)c * L_CHUNK;
    #pragma unroll 4
    for (int i = 0; i < L_CHUNK; i++) {
        const size_t t = tbase + i;
        float4 xv4 = __ldcs(&x4[t * (D_DIM / 4) + d4]);
        float xv[4] = {xv4.x, xv4.y, xv4.z, xv4.w};
        float nv[4];
        #pragma unroll
        for (int k = 0; k < 4; k++) {
            mu[k] = fmaf(ETA_MU_F, xv[k] - mu[k], mu[k]);          // mu += eta*(x-mu)
            float dd = xv[k] - mu[k];
            var[k] = fmaf(ETA_V_F, dd * dd, CV_F * var[k]);         // 0.98*var + 0.02*dd^2
            nv[k] = dd * rsqrtf(var[k]);                            // (x-mu)/sqrt(var)
        }
        __stcs(&norm[t * (D_DIM / 4) + d4],
               make_float4(nv[0], nv[1], nv[2], nv[3]));
        __stcs(&info[t * (2 * D_DIM / 4) + d4],
               make_float4(mu[0], mu[1], mu[2], mu[3]));
        __stcs(&info[t * (2 * D_DIM / 4) + (D_DIM / 4) + d4],
               make_float4(var[0], var[1], var[2], var[3]));
    }
}

extern "C" void kernel_launch(void* const* d_in, const int* in_sizes, int n_in,
                              void* d_out, int out_size) {
    const float* x = (const float*)d_in[0];
    const float4* x4 = (const float4*)d_in[0];
    float4* out4 = (float4*)d_out;

    p1_kernel<<<dim3(D_DIM / 256, C_CHUNKS), 256>>>(x);
    p2a_kernel<<<(NSUP * D_DIM) / 256, 256>>>();
    p2b_kernel<<<D_DIM / 256, 256>>>();
    p2c_kernel<<<(NSUP * D_DIM) / 256, 256>>>();
    p5_kernel<<<dim3((D_DIM / 4) / 128, C_CHUNKS), 128>>>(x4, out4);
}